// round 3
// baseline (speedup 1.0000x reference)
#include <cuda_runtime.h>

// Noisy LIF spiking neuron scan — R3: CH=2 (moderate MLP, low regs) + fine grid.
//   u = 0.5*u + x[t] - 0.5*noise[t] ; o = (u > 1) ; u = o ? 0 : u
//
// 768 MB irreducible HBM traffic; pure stream. R1 (rolled, regs=28, occ 82%,
// MLP~2) hit DRAM=84.1%. R2 (CH=4, regs=41, occ 52%, MLP~8) hit 82.4%:
// per-thread batching cost more occupancy than it bought in-flight loads.
// R3 takes the middle: 4 LDG.128 in flight per thread, regs ~33, occ ~75%,
// maximizing SM-wide outstanding loads. tpb=128/2048 CTAs kept from R2
// (it halved the timed-vs-ncu overhead gap).

static constexpr int B  = 16;
static constexpr int T  = 64;
static constexpr int N  = 65536;
static constexpr int N4 = N / 4;     // float4 lanes per (b, t) row
static constexpr int CH = 2;         // timesteps per load batch

__global__ __launch_bounds__(128) void lif_kernel(
    const float4* __restrict__ x,
    const float4* __restrict__ noise,
    float4* __restrict__ out)
{
    int idx = blockIdx.x * blockDim.x + threadIdx.x;   // 0 .. B*N4-1
    if (idx >= B * N4) return;

    int b  = idx / N4;
    int n4 = idx % N4;

    const size_t base = (size_t)b * T * N4 + n4;
    const float4* __restrict__ xp = x     + base;
    const float4* __restrict__ np = noise + base;
    float4*       __restrict__ op = out   + base;

    float ux = 0.f, uy = 0.f, uz = 0.f, uw = 0.f;

#pragma unroll
    for (int t0 = 0; t0 < T; t0 += CH) {
        float4 xv[CH], nv[CH];

        // 2*CH = 4 independent LDG.128 front-batched per chunk.
#pragma unroll
        for (int j = 0; j < CH; j++) {
            xv[j] = __ldcs(xp + (t0 + j) * N4);
            nv[j] = __ldcs(np + (t0 + j) * N4);
        }

#pragma unroll
        for (int j = 0; j < CH; j++) {
            float4 o;

            ux  = fmaf(0.5f, ux, xv[j].x) - 0.5f * nv[j].x;
            o.x = (ux > 1.0f) ? 1.0f : 0.0f;
            ux  = (ux > 1.0f) ? 0.0f : ux;

            uy  = fmaf(0.5f, uy, xv[j].y) - 0.5f * nv[j].y;
            o.y = (uy > 1.0f) ? 1.0f : 0.0f;
            uy  = (uy > 1.0f) ? 0.0f : uy;

            uz  = fmaf(0.5f, uz, xv[j].z) - 0.5f * nv[j].z;
            o.z = (uz > 1.0f) ? 1.0f : 0.0f;
            uz  = (uz > 1.0f) ? 0.0f : uz;

            uw  = fmaf(0.5f, uw, xv[j].w) - 0.5f * nv[j].w;
            o.w = (uw > 1.0f) ? 1.0f : 0.0f;
            uw  = (uw > 1.0f) ? 0.0f : uw;

            __stcs(op + (t0 + j) * N4, o);
        }
    }
}

extern "C" void kernel_launch(void* const* d_in, const int* in_sizes, int n_in,
                              void* d_out, int out_size)
{
    const float4* x     = (const float4*)d_in[0];
    const float4* noise = (const float4*)d_in[1];
    float4*       out   = (float4*)d_out;

    const int total_threads = B * N4;                    // 262144
    const int tpb = 128;
    const int blocks = (total_threads + tpb - 1) / tpb;  // 2048

    lif_kernel<<<blocks, tpb>>>(x, noise, out);
}

// round 4
// speedup vs baseline: 1.0244x; 1.0244x over previous
#include <cuda_runtime.h>

// Noisy LIF spiking neuron scan — R4: R1 config (tpb=256, rolled) + depth-1
// software prefetch pipeline.
//   u = 0.5*u + x[t] - 0.5*noise[t] ; o = (u > 1) ; u = o ? 0 : u
//
// Surface mapped in R1-R3: per-thread load batching (CH=2/4) always lost;
// tpb=256 beats tpb=128 at equal occupancy (ncu 115.0 vs 119.1). This round
// keeps the winning shape and prefetches t+1's two LDG.128 before the
// compute+STG of step t, so loads never serialize behind the 12-cyc
// STG.128 issue. regs ~35 -> occ still high.

static constexpr int B  = 16;
static constexpr int T  = 64;
static constexpr int N  = 65536;
static constexpr int N4 = N / 4;     // float4 lanes per (b, t) row

__global__ __launch_bounds__(256) void lif_kernel(
    const float4* __restrict__ x,
    const float4* __restrict__ noise,
    float4* __restrict__ out)
{
    int idx = blockIdx.x * blockDim.x + threadIdx.x;   // 0 .. B*N4-1
    if (idx >= B * N4) return;

    int b  = idx >> 14;          // / N4 (16384)
    int n4 = idx & (N4 - 1);     // % N4

    const size_t base = (size_t)b * T * N4 + n4;
    const float4* __restrict__ xp = x     + base;
    const float4* __restrict__ np = noise + base;
    float4*       __restrict__ op = out   + base;

    float ux = 0.f, uy = 0.f, uz = 0.f, uw = 0.f;

    // Prologue: prefetch t=0.
    float4 xv = __ldcs(xp);
    float4 nv = __ldcs(np);

#pragma unroll
    for (int t = 0; t < T; t++) {
        // Prefetch next timestep before touching this one.
        float4 xn, nn;
        if (t + 1 < T) {
            xn = __ldcs(xp + (t + 1) * N4);
            nn = __ldcs(np + (t + 1) * N4);
        }

        float4 o;

        ux  = fmaf(0.5f, ux, xv.x) - 0.5f * nv.x;
        o.x = (ux > 1.0f) ? 1.0f : 0.0f;
        ux  = (ux > 1.0f) ? 0.0f : ux;

        uy  = fmaf(0.5f, uy, xv.y) - 0.5f * nv.y;
        o.y = (uy > 1.0f) ? 1.0f : 0.0f;
        uy  = (uy > 1.0f) ? 0.0f : uy;

        uz  = fmaf(0.5f, uz, xv.z) - 0.5f * nv.z;
        o.z = (uz > 1.0f) ? 1.0f : 0.0f;
        uz  = (uz > 1.0f) ? 0.0f : uz;

        uw  = fmaf(0.5f, uw, xv.w) - 0.5f * nv.w;
        o.w = (uw > 1.0f) ? 1.0f : 0.0f;
        uw  = (uw > 1.0f) ? 0.0f : uw;

        __stcs(op + t * N4, o);

        xv = xn;
        nv = nn;
    }
}

extern "C" void kernel_launch(void* const* d_in, const int* in_sizes, int n_in,
                              void* d_out, int out_size)
{
    const float4* x     = (const float4*)d_in[0];
    const float4* noise = (const float4*)d_in[1];
    float4*       out   = (float4*)d_out;

    const int total_threads = B * N4;                    // 262144
    const int tpb = 256;
    const int blocks = (total_threads + tpb - 1) / tpb;  // 1024

    lif_kernel<<<blocks, tpb>>>(x, noise, out);
}